// round 4
// baseline (speedup 1.0000x reference)
#include <cuda_runtime.h>
#include <cuda_bf16.h>

#define HDIM 1024
#define VDIM 50257
#define SDIM 4096

// ---------------- scratch (no allocations allowed) ----------------
__device__ float g_hnew[HDIM];
__device__ float g_context[HDIM];
__device__ float g_scores[SDIM];
__device__ float g_cpart[32 * HDIM];
__device__ float g_lse[1];

// ---------------- reduction helpers ----------------
__device__ __forceinline__ float warpSum(float v) {
#pragma unroll
    for (int o = 16; o > 0; o >>= 1) v += __shfl_xor_sync(0xffffffffu, v, o);
    return v;
}
__device__ __forceinline__ float warpMax(float v) {
#pragma unroll
    for (int o = 16; o > 0; o >>= 1) v = fmaxf(v, __shfl_xor_sync(0xffffffffu, v, o));
    return v;
}
__device__ __forceinline__ float dot4(float4 a, float4 b) {
    return a.x * b.x + a.y * b.y + a.z * b.z + a.w * b.w;
}

// ---------------- kernel 1: GRU cell, one block per h element ----------------
__global__ __launch_bounds__(256) void k_gru(
    const int* __restrict__ word_input,
    const float* __restrict__ last_context,
    const float* __restrict__ last_hidden,
    const float* __restrict__ embedding,
    const float* __restrict__ w_ih,
    const float* __restrict__ w_hh,
    const float* __restrict__ b_ih,
    const float* __restrict__ b_hh,
    float* __restrict__ hnew_out)
{
    __shared__ float sx[2 * HDIM];
    __shared__ float sh[HDIM];
    __shared__ float rbuf[6][8];

    const int j = blockIdx.x;
    const int t = threadIdx.x;
    const int word = word_input[0];
    const float* erow = embedding + (size_t)word * HDIM;

    for (int k = t; k < HDIM; k += 256) {
        sx[k]        = erow[k];
        sx[HDIM + k] = last_context[k];
        sh[k]        = last_hidden[k];
    }
    __syncthreads();

    const float4* x4 = (const float4*)sx;
    const float4* h4 = (const float4*)sh;
    const float4* wr = (const float4*)(w_ih + (size_t)j * (2 * HDIM));
    const float4* wz = (const float4*)(w_ih + (size_t)(j + HDIM) * (2 * HDIM));
    const float4* wn = (const float4*)(w_ih + (size_t)(j + 2 * HDIM) * (2 * HDIM));
    const float4* ur = (const float4*)(w_hh + (size_t)j * HDIM);
    const float4* uz = (const float4*)(w_hh + (size_t)(j + HDIM) * HDIM);
    const float4* un = (const float4*)(w_hh + (size_t)(j + 2 * HDIM) * HDIM);

    float a0 = 0.f, a1 = 0.f, a2 = 0.f, c0 = 0.f, c1 = 0.f, c2 = 0.f;
#pragma unroll
    for (int i = t; i < 512; i += 256) {
        float4 xv = x4[i];
        a0 += dot4(wr[i], xv);
        a1 += dot4(wz[i], xv);
        a2 += dot4(wn[i], xv);
    }
    {
        int i = t;  // 256 threads, 256 float4 => exactly one each
        float4 hv = h4[i];
        c0 += dot4(ur[i], hv);
        c1 += dot4(uz[i], hv);
        c2 += dot4(un[i], hv);
    }

    a0 = warpSum(a0); a1 = warpSum(a1); a2 = warpSum(a2);
    c0 = warpSum(c0); c1 = warpSum(c1); c2 = warpSum(c2);
    const int lane = t & 31, w = t >> 5;
    if (lane == 0) {
        rbuf[0][w] = a0; rbuf[1][w] = a1; rbuf[2][w] = a2;
        rbuf[3][w] = c0; rbuf[4][w] = c1; rbuf[5][w] = c2;
    }
    __syncthreads();
    if (t == 0) {
        float s[6];
#pragma unroll
        for (int q = 0; q < 6; q++) {
            float acc = 0.f;
#pragma unroll
            for (int p = 0; p < 8; p++) acc += rbuf[q][p];
            s[q] = acc;
        }
        float gir = s[0] + b_ih[j];
        float giz = s[1] + b_ih[j + HDIM];
        float gin = s[2] + b_ih[j + 2 * HDIM];
        float ghr = s[3] + b_hh[j];
        float ghz = s[4] + b_hh[j + HDIM];
        float ghn = s[5] + b_hh[j + 2 * HDIM];
        float r = 1.f / (1.f + expf(-(gir + ghr)));
        float z = 1.f / (1.f + expf(-(giz + ghz)));
        float n = tanhf(gin + r * ghn);
        float hn = (1.f - z) * n + z * sh[j];
        g_hnew[j] = hn;
        hnew_out[j] = hn;
    }
}

// ---------------- kernel 2: attention scores, one block per s ----------------
__global__ __launch_bounds__(256) void k_scores(const float* __restrict__ enc)
{
    const int s = blockIdx.x;
    const int t = threadIdx.x;
    const float4* e4 = (const float4*)(enc + (size_t)s * HDIM);
    const float4* h4 = (const float4*)g_hnew;
    float acc = dot4(e4[t], h4[t]);  // 256 threads x 1 float4 = 1024 floats
    acc = warpSum(acc);
    __shared__ float rb[8];
    if ((t & 31) == 0) rb[t >> 5] = acc;
    __syncthreads();
    if (t == 0) {
        float a = 0.f;
#pragma unroll
        for (int p = 0; p < 8; p++) a += rb[p];
        g_scores[s] = a;
    }
}

// ---------------- kernel 3: softmax over S=4096, single block ----------------
__global__ __launch_bounds__(1024) void k_softmax(float* __restrict__ attn_out)
{
    const int t = threadIdx.x;
    float v0 = g_scores[t];
    float v1 = g_scores[t + 1024];
    float v2 = g_scores[t + 2048];
    float v3 = g_scores[t + 3072];

    __shared__ float rb[32];
    __shared__ float bcast[2];

    float m = fmaxf(fmaxf(v0, v1), fmaxf(v2, v3));
    m = warpMax(m);
    if ((t & 31) == 0) rb[t >> 5] = m;
    __syncthreads();
    if (t < 32) {
        float x = warpMax(rb[t]);
        if (t == 0) bcast[0] = x;
    }
    __syncthreads();
    const float M = bcast[0];
    float e0 = expf(v0 - M), e1 = expf(v1 - M), e2 = expf(v2 - M), e3 = expf(v3 - M);
    float s = e0 + e1 + e2 + e3;
    s = warpSum(s);
    __syncthreads();  // rb reads from phase 1 done before rewrite
    if ((t & 31) == 0) rb[t >> 5] = s;
    __syncthreads();
    if (t < 32) {
        float x = warpSum(rb[t]);
        if (t == 0) bcast[1] = x;
    }
    __syncthreads();
    const float inv = 1.f / bcast[1];
    attn_out[t]        = e0 * inv;
    attn_out[t + 1024] = e1 * inv;
    attn_out[t + 2048] = e2 * inv;
    attn_out[t + 3072] = e3 * inv;
}

// ---------------- kernel 4: context partials (split S across blocks) ----------------
__global__ __launch_bounds__(256) void k_ctx_part(const float* __restrict__ enc,
                                                  const float* __restrict__ attn)
{
    __shared__ float sa[128];
    const int k  = blockIdx.x * 256 + threadIdx.x;  // 4 blocks in x cover HDIM
    const int sc = blockIdx.y;                      // 32 S-chunks of 128
    const int s0 = sc * 128;
    if (threadIdx.x < 128) sa[threadIdx.x] = attn[s0 + threadIdx.x];
    __syncthreads();
    float acc = 0.f;
#pragma unroll 4
    for (int s = 0; s < 128; s++)
        acc += sa[s] * enc[(size_t)(s0 + s) * HDIM + k];
    g_cpart[sc * HDIM + k] = acc;
}

// ---------------- kernel 5: reduce context partials ----------------
__global__ __launch_bounds__(256) void k_ctx_red(float* __restrict__ ctx_out)
{
    const int k = blockIdx.x * 256 + threadIdx.x;
    float acc = 0.f;
#pragma unroll
    for (int p = 0; p < 32; p++) acc += g_cpart[p * HDIM + k];
    g_context[k] = acc;
    ctx_out[k] = acc;
}

// ---------------- kernel 6: output projection (dominant, 412 MB) ----------------
// one warp per vocab row; 16 float4 loads per lane for MLP
__global__ __launch_bounds__(256) void k_logits(const float* __restrict__ out_w,
                                                const float* __restrict__ out_b,
                                                float* __restrict__ logits)
{
    __shared__ float sy[2 * HDIM];
    const int t = threadIdx.x;
    for (int k = t; k < HDIM; k += 256) {
        sy[k]        = g_hnew[k];
        sy[HDIM + k] = g_context[k];
    }
    __syncthreads();
    const int lane = t & 31, w = t >> 5;
    const int r = blockIdx.x * 8 + w;
    if (r >= VDIM) return;
    const float4* w4 = (const float4*)(out_w + (size_t)r * (2 * HDIM));
    const float4* y4 = (const float4*)sy;
    float acc = 0.f;
#pragma unroll
    for (int i = lane; i < 512; i += 32)
        acc += dot4(w4[i], y4[i]);
    acc = warpSum(acc);
    if (lane == 0) logits[r] = acc + out_b[r];
}

// ---------------- kernel 7: log-sum-exp over V, single block ----------------
__global__ __launch_bounds__(1024) void k_lse(const float* __restrict__ logits)
{
    const int t = threadIdx.x;
    __shared__ float rb[32];
    __shared__ float bc;
    float m = -1e30f;
    for (int v = t; v < VDIM; v += 1024) m = fmaxf(m, logits[v]);
    m = warpMax(m);
    if ((t & 31) == 0) rb[t >> 5] = m;
    __syncthreads();
    if (t < 32) {
        float x = warpMax(rb[t]);
        if (t == 0) bc = x;
    }
    __syncthreads();
    const float M = bc;
    float s = 0.f;
    for (int v = t; v < VDIM; v += 1024) s += expf(logits[v] - M);
    s = warpSum(s);
    __syncthreads();
    if ((t & 31) == 0) rb[t >> 5] = s;
    __syncthreads();
    if (t == 0) {
        float a = 0.f;
#pragma unroll
        for (int p = 0; p < 32; p++) a += rb[p];
        g_lse[0] = M + logf(a);
    }
}

// ---------------- kernel 8: subtract lse in place ----------------
__global__ __launch_bounds__(256) void k_sub(float* __restrict__ out)
{
    const int v = blockIdx.x * 256 + threadIdx.x;
    if (v < VDIM) out[v] -= g_lse[0];
}

// ---------------- launch ----------------
extern "C" void kernel_launch(void* const* d_in, const int* in_sizes, int n_in,
                              void* d_out, int out_size)
{
    const int*   word         = (const int*)d_in[0];
    const float* last_context = (const float*)d_in[1];
    const float* last_hidden  = (const float*)d_in[2];
    const float* enc          = (const float*)d_in[3];
    const float* embedding    = (const float*)d_in[4];
    const float* w_ih         = (const float*)d_in[5];
    const float* w_hh         = (const float*)d_in[6];
    const float* b_ih         = (const float*)d_in[7];
    const float* b_hh         = (const float*)d_in[8];
    const float* out_w        = (const float*)d_in[9];
    const float* out_b        = (const float*)d_in[10];

    float* out      = (float*)d_out;
    float* o_logits = out;                    // [V]   log_softmax output
    float* o_ctx    = out + VDIM;             // [H]   context
    float* o_hnew   = out + VDIM + HDIM;      // [H]   h_new
    float* o_attn   = out + VDIM + 2 * HDIM;  // [S]   attn

    k_gru<<<HDIM, 256>>>(word, last_context, last_hidden, embedding,
                         w_ih, w_hh, b_ih, b_hh, o_hnew);
    k_scores<<<SDIM, 256>>>(enc);
    k_softmax<<<1, 1024>>>(o_attn);
    k_ctx_part<<<dim3(4, 32), 256>>>(enc, o_attn);
    k_ctx_red<<<4, 256>>>(o_ctx);
    k_logits<<<(VDIM + 7) / 8, 256>>>(out_w, out_b, o_logits);
    k_lse<<<1, 1024>>>(o_logits);
    k_sub<<<(VDIM + 255) / 256, 256>>>(o_logits);
}

// round 5
// speedup vs baseline: 1.1099x; 1.1099x over previous
#include <cuda_runtime.h>
#include <cuda_bf16.h>

#define HDIM 1024
#define VDIM 50257
#define SDIM 4096
#define NCHUNK 256          // S-chunks for context partials
#define CHUNK  (SDIM / NCHUNK)   // 16

// ---------------- scratch (no allocations allowed) ----------------
__device__ float g_hnew[HDIM];
__device__ float g_context[HDIM];
__device__ float g_scores[SDIM];
__device__ float g_cpart[NCHUNK * HDIM];
__device__ float g_lse[1];

// ---------------- reduction helpers ----------------
__device__ __forceinline__ float warpSum(float v) {
#pragma unroll
    for (int o = 16; o > 0; o >>= 1) v += __shfl_xor_sync(0xffffffffu, v, o);
    return v;
}
__device__ __forceinline__ float warpMax(float v) {
#pragma unroll
    for (int o = 16; o > 0; o >>= 1) v = fmaxf(v, __shfl_xor_sync(0xffffffffu, v, o));
    return v;
}
__device__ __forceinline__ float dot4(float4 a, float4 b) {
    return a.x * b.x + a.y * b.y + a.z * b.z + a.w * b.w;
}

// ---------------- kernel 1: GRU cell, one block per h element ----------------
__global__ __launch_bounds__(256) void k_gru(
    const int* __restrict__ word_input,
    const float* __restrict__ last_context,
    const float* __restrict__ last_hidden,
    const float* __restrict__ embedding,
    const float* __restrict__ w_ih,
    const float* __restrict__ w_hh,
    const float* __restrict__ b_ih,
    const float* __restrict__ b_hh,
    float* __restrict__ hnew_out)
{
    __shared__ float sx[2 * HDIM];
    __shared__ float sh[HDIM];
    __shared__ float rbuf[6][8];

    const int j = blockIdx.x;
    const int t = threadIdx.x;
    const int word = word_input[0];
    const float* erow = embedding + (size_t)word * HDIM;

    for (int k = t; k < HDIM; k += 256) {
        sx[k]        = erow[k];
        sx[HDIM + k] = last_context[k];
        sh[k]        = last_hidden[k];
    }
    __syncthreads();

    const float4* x4 = (const float4*)sx;
    const float4* h4 = (const float4*)sh;
    const float4* wr = (const float4*)(w_ih + (size_t)j * (2 * HDIM));
    const float4* wz = (const float4*)(w_ih + (size_t)(j + HDIM) * (2 * HDIM));
    const float4* wn = (const float4*)(w_ih + (size_t)(j + 2 * HDIM) * (2 * HDIM));
    const float4* ur = (const float4*)(w_hh + (size_t)j * HDIM);
    const float4* uz = (const float4*)(w_hh + (size_t)(j + HDIM) * HDIM);
    const float4* un = (const float4*)(w_hh + (size_t)(j + 2 * HDIM) * HDIM);

    float a0 = 0.f, a1 = 0.f, a2 = 0.f, c0 = 0.f, c1 = 0.f, c2 = 0.f;
#pragma unroll
    for (int i = t; i < 512; i += 256) {
        float4 xv = x4[i];
        a0 += dot4(__ldcs(&wr[i]), xv);
        a1 += dot4(__ldcs(&wz[i]), xv);
        a2 += dot4(__ldcs(&wn[i]), xv);
    }
    {
        int i = t;  // 256 threads, 256 float4 => exactly one each
        float4 hv = h4[i];
        c0 += dot4(__ldcs(&ur[i]), hv);
        c1 += dot4(__ldcs(&uz[i]), hv);
        c2 += dot4(__ldcs(&un[i]), hv);
    }

    a0 = warpSum(a0); a1 = warpSum(a1); a2 = warpSum(a2);
    c0 = warpSum(c0); c1 = warpSum(c1); c2 = warpSum(c2);
    const int lane = t & 31, w = t >> 5;
    if (lane == 0) {
        rbuf[0][w] = a0; rbuf[1][w] = a1; rbuf[2][w] = a2;
        rbuf[3][w] = c0; rbuf[4][w] = c1; rbuf[5][w] = c2;
    }
    __syncthreads();
    if (t == 0) {
        float s[6];
#pragma unroll
        for (int q = 0; q < 6; q++) {
            float acc = 0.f;
#pragma unroll
            for (int p = 0; p < 8; p++) acc += rbuf[q][p];
            s[q] = acc;
        }
        float gir = s[0] + b_ih[j];
        float giz = s[1] + b_ih[j + HDIM];
        float gin = s[2] + b_ih[j + 2 * HDIM];
        float ghr = s[3] + b_hh[j];
        float ghz = s[4] + b_hh[j + HDIM];
        float ghn = s[5] + b_hh[j + 2 * HDIM];
        float r = 1.f / (1.f + expf(-(gir + ghr)));
        float z = 1.f / (1.f + expf(-(giz + ghz)));
        float n = tanhf(gin + r * ghn);
        float hn = (1.f - z) * n + z * sh[j];
        g_hnew[j] = hn;
        hnew_out[j] = hn;
    }
}

// ---------------- kernel 2: attention scores, one block per s ----------------
// enc is deliberately default-cached: it is re-read by k_ctx_part from L2.
__global__ __launch_bounds__(256) void k_scores(const float* __restrict__ enc)
{
    const int s = blockIdx.x;
    const int t = threadIdx.x;
    const float4* e4 = (const float4*)(enc + (size_t)s * HDIM);
    const float4* h4 = (const float4*)g_hnew;
    float acc = dot4(e4[t], h4[t]);  // 256 threads x 1 float4 = 1024 floats
    acc = warpSum(acc);
    __shared__ float rb[8];
    if ((t & 31) == 0) rb[t >> 5] = acc;
    __syncthreads();
    if (t == 0) {
        float a = 0.f;
#pragma unroll
        for (int p = 0; p < 8; p++) a += rb[p];
        g_scores[s] = a;
    }
}

// ---------------- kernel 3: softmax over S=4096, single block ----------------
__global__ __launch_bounds__(1024) void k_softmax(float* __restrict__ attn_out)
{
    const int t = threadIdx.x;
    float v0 = g_scores[t];
    float v1 = g_scores[t + 1024];
    float v2 = g_scores[t + 2048];
    float v3 = g_scores[t + 3072];

    __shared__ float rb[32];
    __shared__ float bcast[2];

    float m = fmaxf(fmaxf(v0, v1), fmaxf(v2, v3));
    m = warpMax(m);
    if ((t & 31) == 0) rb[t >> 5] = m;
    __syncthreads();
    if (t < 32) {
        float x = warpMax(rb[t]);
        if (t == 0) bcast[0] = x;
    }
    __syncthreads();
    const float M = bcast[0];
    float e0 = expf(v0 - M), e1 = expf(v1 - M), e2 = expf(v2 - M), e3 = expf(v3 - M);
    float s = e0 + e1 + e2 + e3;
    s = warpSum(s);
    __syncthreads();
    if ((t & 31) == 0) rb[t >> 5] = s;
    __syncthreads();
    if (t < 32) {
        float x = warpSum(rb[t]);
        if (t == 0) bcast[1] = x;
    }
    __syncthreads();
    const float inv = 1.f / bcast[1];
    attn_out[t]        = e0 * inv;
    attn_out[t + 1024] = e1 * inv;
    attn_out[t + 2048] = e2 * inv;
    attn_out[t + 3072] = e3 * inv;
}

// ---------------- kernel 4: context partials ----------------
// grid = (4, NCHUNK): 1024 blocks. Each block handles 256 columns x CHUNK=16 rows.
// Fully unrolled: 16 independent loads in flight per thread (MLP=16).
__global__ __launch_bounds__(256) void k_ctx_part(const float* __restrict__ enc,
                                                  const float* __restrict__ attn)
{
    __shared__ float sa[CHUNK];
    const int k  = blockIdx.x * 256 + threadIdx.x;  // column 0..1023
    const int sc = blockIdx.y;                      // S-chunk 0..255
    const int s0 = sc * CHUNK;
    if (threadIdx.x < CHUNK) sa[threadIdx.x] = attn[s0 + threadIdx.x];
    __syncthreads();
    const float* base = enc + (size_t)s0 * HDIM + k;
    float v[CHUNK];
#pragma unroll
    for (int s = 0; s < CHUNK; s++) v[s] = base[(size_t)s * HDIM];
    float acc = 0.f;
#pragma unroll
    for (int s = 0; s < CHUNK; s++) acc += sa[s] * v[s];
    g_cpart[sc * HDIM + k] = acc;
}

// ---------------- kernel 5: reduce context partials ----------------
__global__ __launch_bounds__(256) void k_ctx_red(float* __restrict__ ctx_out)
{
    const int k = blockIdx.x * 256 + threadIdx.x;
    float acc = 0.f;
#pragma unroll
    for (int p = 0; p < NCHUNK; p++) acc += g_cpart[p * HDIM + k];
    g_context[k] = acc;
    ctx_out[k] = acc;
}

// ---------------- kernel 6: output projection (dominant, 412 MB) ----------------
// one warp per vocab row; 16 float4 streaming loads per lane
__global__ __launch_bounds__(256) void k_logits(const float* __restrict__ out_w,
                                                const float* __restrict__ out_b,
                                                float* __restrict__ logits)
{
    __shared__ float sy[2 * HDIM];
    const int t = threadIdx.x;
    for (int k = t; k < HDIM; k += 256) {
        sy[k]        = g_hnew[k];
        sy[HDIM + k] = g_context[k];
    }
    __syncthreads();
    const int lane = t & 31, w = t >> 5;
    const int r = blockIdx.x * 8 + w;
    if (r >= VDIM) return;
    const float4* w4 = (const float4*)(out_w + (size_t)r * (2 * HDIM));
    const float4* y4 = (const float4*)sy;
    float acc = 0.f;
#pragma unroll
    for (int i = lane; i < 512; i += 32)
        acc += dot4(__ldcs(&w4[i]), y4[i]);
    acc = warpSum(acc);
    if (lane == 0) logits[r] = acc + out_b[r];
}

// ---------------- kernel 7: log-sum-exp over V, single block ----------------
__global__ __launch_bounds__(1024) void k_lse(const float* __restrict__ logits)
{
    const int t = threadIdx.x;
    __shared__ float rb[32];
    __shared__ float bc;
    float m = -1e30f;
    for (int v = t; v < VDIM; v += 1024) m = fmaxf(m, logits[v]);
    m = warpMax(m);
    if ((t & 31) == 0) rb[t >> 5] = m;
    __syncthreads();
    if (t < 32) {
        float x = warpMax(rb[t]);
        if (t == 0) bc = x;
    }
    __syncthreads();
    const float M = bc;
    float s = 0.f;
    for (int v = t; v < VDIM; v += 1024) s += expf(logits[v] - M);
    s = warpSum(s);
    __syncthreads();
    if ((t & 31) == 0) rb[t >> 5] = s;
    __syncthreads();
    if (t == 0) {
        float a = 0.f;
#pragma unroll
        for (int p = 0; p < 32; p++) a += rb[p];
        g_lse[0] = M + logf(a);
    }
}

// ---------------- kernel 8: subtract lse in place ----------------
__global__ __launch_bounds__(256) void k_sub(float* __restrict__ out)
{
    const int v = blockIdx.x * 256 + threadIdx.x;
    if (v < VDIM) out[v] -= g_lse[0];
}

// ---------------- launch ----------------
extern "C" void kernel_launch(void* const* d_in, const int* in_sizes, int n_in,
                              void* d_out, int out_size)
{
    const int*   word         = (const int*)d_in[0];
    const float* last_context = (const float*)d_in[1];
    const float* last_hidden  = (const float*)d_in[2];
    const float* enc          = (const float*)d_in[3];
    const float* embedding    = (const float*)d_in[4];
    const float* w_ih         = (const float*)d_in[5];
    const float* w_hh         = (const float*)d_in[6];
    const float* b_ih         = (const float*)d_in[7];
    const float* b_hh         = (const float*)d_in[8];
    const float* out_w        = (const float*)d_in[9];
    const float* out_b        = (const float*)d_in[10];

    float* out      = (float*)d_out;
    float* o_logits = out;                    // [V]   log_softmax output
    float* o_ctx    = out + VDIM;             // [H]   context
    float* o_hnew   = out + VDIM + HDIM;      // [H]   h_new
    float* o_attn   = out + VDIM + 2 * HDIM;  // [S]   attn

    k_gru<<<HDIM, 256>>>(word, last_context, last_hidden, embedding,
                         w_ih, w_hh, b_ih, b_hh, o_hnew);
    k_scores<<<SDIM, 256>>>(enc);
    k_softmax<<<1, 1024>>>(o_attn);
    k_ctx_part<<<dim3(4, NCHUNK), 256>>>(enc, o_attn);
    k_ctx_red<<<4, 256>>>(o_ctx);
    k_logits<<<(VDIM + 7) / 8, 256>>>(out_w, out_b, o_logits);
    k_lse<<<1, 1024>>>(o_logits);
    k_sub<<<(VDIM + 255) / 256, 256>>>(o_logits);
}